// round 3
// baseline (speedup 1.0000x reference)
#include <cuda_runtime.h>
#include <math.h>

#define NNODE 50000
#define NEDGE 800000
#define FIN   128
#define FOUT  64
#define NEG_SLOPE 0.2f
#define NB_SCAN 49            // ceil(NNODE/1024)

// ---------------- scratch (device globals: no allocation allowed) -------------
__device__ float g_xl[NNODE * FOUT];
__device__ float g_xr[NNODE * FOUT];
__device__ int   g_deg[NNODE];
__device__ int   g_off[NNODE];
__device__ int   g_cursor[NNODE];
__device__ int   g_csr[NEDGE];
__device__ int   g_bsum[NB_SCAN];
__device__ int   g_is64;

// ---------------- init: zero counters + detect edge_index dtype --------------
// int64 detection: if the buffer is真 int64, every 8-byte value is in
// [0, NNODE). If it is int32, the upper half of each pair is another random
// index (virtually never all-zero across 256 samples), so the check fails.
__global__ void init_kernel(const void* __restrict__ ei) {
    int i = blockIdx.x * blockDim.x + threadIdx.x;
    for (int k = i; k < NNODE; k += gridDim.x * blockDim.x) {
        g_deg[k] = 0;
        g_cursor[k] = 0;
    }
    if (blockIdx.x == 0 && threadIdx.x < 32) {
        const long long* p = (const long long*)ei;
        int lane = threadIdx.x;
        int ok = 1;
#pragma unroll
        for (int j = 0; j < 8; ++j) {
            long long v = p[lane * 8 + j];
            if (v < 0 || v >= (long long)NNODE) ok = 0;
        }
        unsigned all = __ballot_sync(0xffffffffu, ok);
        if (lane == 0) g_is64 = (all == 0xffffffffu) ? 1 : 0;
    }
}

// ---------------- GEMM: xl = x@Wl^T+bl, xr = x@Wr^T+br -----------------------
// 256 threads, 32 x-rows per block, two passes (Wl then Wr).
// Shared: sX4 [32 rows][32 k4] = 16KB; sW4 [128 k][16 c4] = 32KB (XOR swizzle).
// Thread: c4 = tid&15 (4 output cols), rows r0 = (tid>>4)*2 .. +1 (2 rows).
__global__ void __launch_bounds__(256) gemm_kernel(
        const float* __restrict__ x,
        const float* __restrict__ Wl,
        const float* __restrict__ bl,
        const float* __restrict__ Wr,
        const float* __restrict__ br) {
    __shared__ float4 sX4[32 * 32];   // 16384 B
    __shared__ float4 sW4[128 * 16];  // 32768 B  (total 48KB static)

    const int tid = threadIdx.x;
    const int rowBase = blockIdx.x * 32;

    const float4* x4 = (const float4*)x;
    for (int i = tid; i < 32 * 32; i += 256) {
        int r = i >> 5, c = i & 31;
        int row = rowBase + r;
        sX4[i] = (row < NNODE) ? x4[row * 32 + c] : make_float4(0.f, 0.f, 0.f, 0.f);
    }

    const int c4 = tid & 15;
    const int r0 = (tid >> 4) * 2;

#pragma unroll
    for (int p = 0; p < 2; ++p) {
        const float* W = p ? Wr : Wl;
        __syncthreads();   // sW reuse guard (and first-pass sX visibility)
        // k-major W with XOR swizzle at float4 granularity:
        // logical sW4[k*16 + c4] -> physical sW4[k*16 + (c4 ^ (k & 15))]
        for (int i = tid; i < 64 * 128; i += 256) {
            int c = i & 63;
            int k = i >> 6;
            float v = W[c * 128 + k];
            int cc4 = c >> 2, cj = c & 3;
            ((float*)&sW4[k * 16 + (cc4 ^ (k & 15))])[cj] = v;
        }
        __syncthreads();

        float4 acc0 = make_float4(0.f, 0.f, 0.f, 0.f);
        float4 acc1 = make_float4(0.f, 0.f, 0.f, 0.f);
#pragma unroll 4
        for (int k4 = 0; k4 < 32; ++k4) {
            float4 xv0 = sX4[r0 * 32 + k4];
            float4 xv1 = sX4[(r0 + 1) * 32 + k4];
#pragma unroll
            for (int j = 0; j < 4; ++j) {
                int k = 4 * k4 + j;
                float4 wv = sW4[k * 16 + (c4 ^ (k & 15))];
                float xs0 = ((const float*)&xv0)[j];
                float xs1 = ((const float*)&xv1)[j];
                acc0.x = fmaf(xs0, wv.x, acc0.x);
                acc0.y = fmaf(xs0, wv.y, acc0.y);
                acc0.z = fmaf(xs0, wv.z, acc0.z);
                acc0.w = fmaf(xs0, wv.w, acc0.w);
                acc1.x = fmaf(xs1, wv.x, acc1.x);
                acc1.y = fmaf(xs1, wv.y, acc1.y);
                acc1.z = fmaf(xs1, wv.z, acc1.z);
                acc1.w = fmaf(xs1, wv.w, acc1.w);
            }
        }

        const float* b = p ? br : bl;
        float4 bias4 = ((const float4*)b)[c4];
        float* dstbuf = p ? g_xr : g_xl;
        int row0 = rowBase + r0;
        if (row0 < NNODE) {
            float4 o = acc0;
            o.x += bias4.x; o.y += bias4.y; o.z += bias4.z; o.w += bias4.w;
            ((float4*)(dstbuf + row0 * 64))[c4] = o;
        }
        if (row0 + 1 < NNODE) {
            float4 o = acc1;
            o.x += bias4.x; o.y += bias4.y; o.z += bias4.z; o.w += bias4.w;
            ((float4*)(dstbuf + (row0 + 1) * 64))[c4] = o;
        }
    }
}

// ---------------- degree histogram -------------------------------------------
__global__ void deg_kernel(const void* __restrict__ ei) {
    const int stride = gridDim.x * blockDim.x;
    const int is64 = g_is64;
    for (int i = blockIdx.x * blockDim.x + threadIdx.x; i < NEDGE; i += stride) {
        int d;
        if (is64) d = (int)((const long long*)ei)[NEDGE + i];
        else      d = ((const int*)ei)[NEDGE + i];
        atomicAdd(&g_deg[d], 1);
    }
}

// ---------------- per-block scan of degrees (writes partial offsets + bsum) ---
__global__ void scan_kernel() {
    int i = blockIdx.x * 1024 + threadIdx.x;
    int v = (i < NNODE) ? g_deg[i] : 0;
    int xx = v;
    int lane = threadIdx.x & 31, wid = threadIdx.x >> 5;
#pragma unroll
    for (int o = 1; o < 32; o <<= 1) {
        int y = __shfl_up_sync(0xffffffffu, xx, o);
        if (lane >= o) xx += y;
    }
    __shared__ int ws[32];
    if (lane == 31) ws[wid] = xx;
    __syncthreads();
    if (wid == 0) {
        int y = ws[lane];
#pragma unroll
        for (int o = 1; o < 32; o <<= 1) {
            int z = __shfl_up_sync(0xffffffffu, y, o);
            if (lane >= o) y += z;
        }
        ws[lane] = y;
    }
    __syncthreads();
    int incl = xx + (wid ? ws[wid - 1] : 0);
    if (i < NNODE) g_off[i] = incl - v;          // block-local exclusive
    if (threadIdx.x == 1023) g_bsum[blockIdx.x] = incl;  // block total
}

// ---------------- inter-block prefix + fixup ---------------------------------
__global__ void scanb_kernel() {
    if (threadIdx.x == 0 && blockIdx.x == 0) {
        int run = 0;
        for (int b = 0; b < NB_SCAN; ++b) {
            int t = g_bsum[b];
            g_bsum[b] = run;
            run += t;
        }
    }
}
__global__ void fixup_kernel() {
    int i = blockIdx.x * 1024 + threadIdx.x;
    if (i < NNODE) g_off[i] += g_bsum[blockIdx.x];
}

// ---------------- scatter edges into CSR (by dst) ----------------------------
__global__ void scatter_kernel(const void* __restrict__ ei) {
    const int stride = gridDim.x * blockDim.x;
    const int is64 = g_is64;
    for (int i = blockIdx.x * blockDim.x + threadIdx.x; i < NEDGE; i += stride) {
        int s, d;
        if (is64) {
            s = (int)((const long long*)ei)[i];
            d = (int)((const long long*)ei)[NEDGE + i];
        } else {
            s = ((const int*)ei)[i];
            d = ((const int*)ei)[NEDGE + i];
        }
        int pos = atomicAdd(&g_cursor[d], 1);
        g_csr[g_off[d] + pos] = s;
    }
}

// ---------------- aggregation: one warp per dst, online softmax --------------
__global__ void aggregate_kernel(const float* __restrict__ att,
                                 const float* __restrict__ bias,
                                 float* __restrict__ out) {
    int gw   = (blockIdx.x * blockDim.x + threadIdx.x) >> 5;
    int lane = threadIdx.x & 31;
    if (gw >= NNODE) return;
    const int dst = gw;

    const float a0 = att[lane];
    const float a1 = att[lane + 32];
    const float xr0 = g_xr[dst * 64 + lane];
    const float xr1 = g_xr[dst * 64 + lane + 32];

    const int start = g_off[dst];
    const int cnt   = g_deg[dst];

    float m = -INFINITY, s = 0.f, acc0 = 0.f, acc1 = 0.f;

    // t = 0 is the self-loop; t in [1, cnt] are CSR edges.
    float v0 = g_xl[dst * 64 + lane];
    float v1 = g_xl[dst * 64 + lane + 32];

    for (int t = 0; t <= cnt; ++t) {
        float cv0 = v0, cv1 = v1;
        if (t < cnt) {                      // prefetch next source row
            int sn = g_csr[start + t];
            v0 = g_xl[sn * 64 + lane];
            v1 = g_xl[sn * 64 + lane + 32];
        }
        float h0 = cv0 + xr0; h0 = h0 > 0.f ? h0 : NEG_SLOPE * h0;
        float h1 = cv1 + xr1; h1 = h1 > 0.f ? h1 : NEG_SLOPE * h1;
        float p = a0 * h0 + a1 * h1;
#pragma unroll
        for (int o = 16; o; o >>= 1) p += __shfl_xor_sync(0xffffffffu, p, o);

        float mn = fmaxf(m, p);
        float cs = __expf(m - mn);   // 0 on the first iteration (m = -inf)
        float ce = __expf(p - mn);
        s    = s * cs + ce;
        acc0 = acc0 * cs + ce * cv0;
        acc1 = acc1 * cs + ce * cv1;
        m = mn;
    }

    float inv = 1.f / s;
    out[dst * 64 + lane]      = fmaxf(acc0 * inv + bias[lane], 0.f);
    out[dst * 64 + lane + 32] = fmaxf(acc1 * inv + bias[lane + 32], 0.f);
}

// ---------------- launch ------------------------------------------------------
extern "C" void kernel_launch(void* const* d_in, const int* in_sizes, int n_in,
                              void* d_out, int out_size) {
    const float* x    = (const float*)d_in[0];
    const float* Wl   = (const float*)d_in[1];
    const float* bl   = (const float*)d_in[2];
    const float* Wr   = (const float*)d_in[3];
    const float* br   = (const float*)d_in[4];
    const float* att  = (const float*)d_in[5];
    const float* bias = (const float*)d_in[6];
    const void*  ei   = (const void*)d_in[7];
    float* out = (float*)d_out;

    init_kernel<<<NB_SCAN, 1024>>>(ei);
    gemm_kernel<<<(NNODE + 31) / 32, 256>>>(x, Wl, bl, Wr, br);
    deg_kernel<<<1184, 256>>>(ei);          // 8 waves of 148 SMs @ 256 thr
    scan_kernel<<<NB_SCAN, 1024>>>();
    scanb_kernel<<<1, 32>>>();
    fixup_kernel<<<NB_SCAN, 1024>>>();
    scatter_kernel<<<1184, 256>>>(ei);
    aggregate_kernel<<<(NNODE * 32 + 255) / 256, 256>>>(att, bias, out);
}

// round 5
// speedup vs baseline: 1.7786x; 1.7786x over previous
#include <cuda_runtime.h>
#include <math.h>
#include <stdint.h>

#define NNODE 50000
#define NEDGE 800000
#define FIN   128
#define FOUT  64
#define NEG_SLOPE 0.2f
#define NB_SCAN 49            // ceil(NNODE/1024)

// ---------------- scratch (device globals: no allocation allowed) -------------
__device__ float g_xl[NNODE * FOUT];
__device__ float g_xr[NNODE * FOUT];
__device__ int   g_deg[NNODE];
__device__ int   g_off[NNODE];
__device__ int   g_cursor[NNODE];
__device__ int   g_csr[NEDGE];
__device__ int   g_bsum[NB_SCAN];
__device__ int   g_is64;

// ---------------- init: zero counters + detect edge_index dtype --------------
__global__ void init_kernel(const void* __restrict__ ei) {
    int i = blockIdx.x * blockDim.x + threadIdx.x;
    for (int k = i; k < NNODE; k += gridDim.x * blockDim.x) {
        g_deg[k] = 0;
        g_cursor[k] = 0;
    }
    if (blockIdx.x == 0 && threadIdx.x < 32) {
        const long long* p = (const long long*)ei;
        int lane = threadIdx.x;
        int ok = 1;
#pragma unroll
        for (int j = 0; j < 8; ++j) {
            long long v = p[lane * 8 + j];
            if (v < 0 || v >= (long long)NNODE) ok = 0;
        }
        unsigned all = __ballot_sync(0xffffffffu, ok);
        if (lane == 0) g_is64 = (all == 0xffffffffu) ? 1 : 0;
    }
}

// ---------------- 3xTF32 tensor-core GEMM (48KB static smem) ------------------
// Per block: 256 thr (8 warps), 32 X-rows, two passes (Wl half, Wr half).
// Warp w: m-tile = (w>>2)*16 rows, n-tile = (w&3)*16 cols (2 n8 frags).
// Smem float4 cells with XOR swizzle: cell(r,c4) -> r*32 + (c4 ^ (r&7)).
// 3xTF32: v = hi + lo (both tf32); acc += hi*hi + hi*lo + lo*hi -> fp32-class
// accuracy on tensor cores.

__device__ __forceinline__ void tf32_split(float v, uint32_t& hi, uint32_t& lo) {
    asm("cvt.rna.tf32.f32 %0, %1;" : "=r"(hi) : "f"(v));
    float l = v - __uint_as_float(hi);
    asm("cvt.rna.tf32.f32 %0, %1;" : "=r"(lo) : "f"(l));
}

__device__ __forceinline__ void mma_tf32(float c[4], const uint32_t a[4],
                                         uint32_t b0, uint32_t b1) {
    asm volatile(
        "mma.sync.aligned.m16n8k8.row.col.f32.tf32.tf32.f32 "
        "{%0,%1,%2,%3}, {%4,%5,%6,%7}, {%8,%9}, {%0,%1,%2,%3};"
        : "+f"(c[0]), "+f"(c[1]), "+f"(c[2]), "+f"(c[3])
        : "r"(a[0]), "r"(a[1]), "r"(a[2]), "r"(a[3]), "r"(b0), "r"(b1));
}

__global__ void __launch_bounds__(256) gemm_kernel(
        const float* __restrict__ x,
        const float* __restrict__ Wl,
        const float* __restrict__ bl,
        const float* __restrict__ Wr,
        const float* __restrict__ br) {
    __shared__ float4 sX4[32 * 32];   // 16 KB: 32 rows x 128 k
    __shared__ float4 sW4[64 * 32];   // 32 KB: 64 cols x 128 k (one W half)

    const int tid = threadIdx.x;
    const int rowBase = blockIdx.x * 32;

    // Load X tile, swizzled. Each warp writes one row => XOR constant per warp.
    const float4* x4 = (const float4*)x;
    for (int i = tid; i < 32 * 32; i += 256) {
        int r = i >> 5, c = i & 31;
        int row = rowBase + r;
        sX4[r * 32 + (c ^ (r & 7))] =
            (row < NNODE) ? x4[row * 32 + c] : make_float4(0.f, 0.f, 0.f, 0.f);
    }

    const int w    = tid >> 5;
    const int lane = tid & 31;
    const int g    = lane >> 2;    // 0..7
    const int tig  = lane & 3;     // 0..3
    const int mw   = (w >> 2) * 16;
    const int nw   = (w & 3) * 16;

#pragma unroll
    for (int p = 0; p < 2; ++p) {
        const float4* w4 = p ? (const float4*)Wr : (const float4*)Wl;
        __syncthreads();   // protect sW reuse (and pass-0 sX visibility)
        for (int i = tid; i < 64 * 32; i += 256) {
            int r = i >> 5, c = i & 31;
            sW4[r * 32 + (c ^ (r & 7))] = w4[r * 32 + c];
        }
        __syncthreads();

        float acc[2][4];
#pragma unroll
        for (int j = 0; j < 2; ++j)
#pragma unroll
            for (int q = 0; q < 4; ++q) acc[j][q] = 0.f;

        const int r0 = mw + g, r1 = mw + 8 + g;

#pragma unroll
        for (int ks = 0; ks < 16; ++ks) {
            const int c4a = 2 * ks;      // float4 cell for k0..k0+3
            const int c4b = 2 * ks + 1;  // float4 cell for k0+4..k0+7
            float af[4];
            af[0] = ((const float*)&sX4[r0 * 32 + (c4a ^ (r0 & 7))])[tig];
            af[1] = ((const float*)&sX4[r1 * 32 + (c4a ^ (r1 & 7))])[tig];
            af[2] = ((const float*)&sX4[r0 * 32 + (c4b ^ (r0 & 7))])[tig];
            af[3] = ((const float*)&sX4[r1 * 32 + (c4b ^ (r1 & 7))])[tig];
            uint32_t ahi[4], alo[4];
#pragma unroll
            for (int q = 0; q < 4; ++q) tf32_split(af[q], ahi[q], alo[q]);

#pragma unroll
            for (int j = 0; j < 2; ++j) {
                const int br_ = nw + j * 8 + g;   // W row (= output col)
                float b0f = ((const float*)&sW4[br_ * 32 + (c4a ^ (br_ & 7))])[tig];
                float b1f = ((const float*)&sW4[br_ * 32 + (c4b ^ (br_ & 7))])[tig];
                uint32_t b0h, b0l, b1h, b1l;
                tf32_split(b0f, b0h, b0l);
                tf32_split(b1f, b1h, b1l);
                mma_tf32(acc[j], ahi, b0h, b1h);   // hi*hi
                mma_tf32(acc[j], ahi, b0l, b1l);   // hi*lo
                mma_tf32(acc[j], alo, b0h, b1h);   // lo*hi
            }
        }

        // Store: c0=(g,cc) c1=(g,cc+1) c2=(g+8,cc) c3=(g+8,cc+1)
        float* dstbuf = p ? g_xr : g_xl;
        const float* bb = p ? br : bl;
#pragma unroll
        for (int j = 0; j < 2; ++j) {
            int cc = nw + j * 8 + 2 * tig;
            float bias0 = bb[cc], bias1 = bb[cc + 1];
            int row0 = rowBase + mw + g;
            if (row0 < NNODE) {
                float2 o = make_float2(acc[j][0] + bias0, acc[j][1] + bias1);
                *(float2*)(dstbuf + row0 * 64 + cc) = o;
            }
            int row1 = row0 + 8;
            if (row1 < NNODE) {
                float2 o = make_float2(acc[j][2] + bias0, acc[j][3] + bias1);
                *(float2*)(dstbuf + row1 * 64 + cc) = o;
            }
        }
    }
}

// ---------------- degree histogram -------------------------------------------
__global__ void deg_kernel(const void* __restrict__ ei) {
    const int stride = gridDim.x * blockDim.x;
    const int is64 = g_is64;
    for (int i = blockIdx.x * blockDim.x + threadIdx.x; i < NEDGE; i += stride) {
        int d;
        if (is64) d = (int)((const long long*)ei)[NEDGE + i];
        else      d = ((const int*)ei)[NEDGE + i];
        atomicAdd(&g_deg[d], 1);
    }
}

// ---------------- per-block scan of degrees ----------------------------------
__global__ void scan_kernel() {
    int i = blockIdx.x * 1024 + threadIdx.x;
    int v = (i < NNODE) ? g_deg[i] : 0;
    int xx = v;
    int lane = threadIdx.x & 31, wid = threadIdx.x >> 5;
#pragma unroll
    for (int o = 1; o < 32; o <<= 1) {
        int y = __shfl_up_sync(0xffffffffu, xx, o);
        if (lane >= o) xx += y;
    }
    __shared__ int ws[32];
    if (lane == 31) ws[wid] = xx;
    __syncthreads();
    if (wid == 0) {
        int y = ws[lane];
#pragma unroll
        for (int o = 1; o < 32; o <<= 1) {
            int z = __shfl_up_sync(0xffffffffu, y, o);
            if (lane >= o) y += z;
        }
        ws[lane] = y;
    }
    __syncthreads();
    int incl = xx + (wid ? ws[wid - 1] : 0);
    if (i < NNODE) g_off[i] = incl - v;                  // block-local exclusive
    if (threadIdx.x == 1023) g_bsum[blockIdx.x] = incl;  // block total
}

// ---------------- fixup: inter-block prefix (computed redundantly) + add -----
__global__ void fixup_kernel() {
    __shared__ int pref;
    if (threadIdx.x == 0) {
        int run = 0;
        for (int b = 0; b < blockIdx.x; ++b) run += g_bsum[b];
        pref = run;
    }
    __syncthreads();
    int i = blockIdx.x * 1024 + threadIdx.x;
    if (i < NNODE) g_off[i] += pref;
}

// ---------------- scatter edges into CSR (by dst) ----------------------------
__global__ void scatter_kernel(const void* __restrict__ ei) {
    const int stride = gridDim.x * blockDim.x;
    const int is64 = g_is64;
    for (int i = blockIdx.x * blockDim.x + threadIdx.x; i < NEDGE; i += stride) {
        int s, d;
        if (is64) {
            s = (int)((const long long*)ei)[i];
            d = (int)((const long long*)ei)[NEDGE + i];
        } else {
            s = ((const int*)ei)[i];
            d = ((const int*)ei)[NEDGE + i];
        }
        int pos = atomicAdd(&g_cursor[d], 1);
        g_csr[g_off[d] + pos] = s;
    }
}

// ---------------- aggregation: one warp per dst, online softmax --------------
__global__ void aggregate_kernel(const float* __restrict__ att,
                                 const float* __restrict__ bias,
                                 float* __restrict__ out) {
    int gw   = (blockIdx.x * blockDim.x + threadIdx.x) >> 5;
    int lane = threadIdx.x & 31;
    if (gw >= NNODE) return;
    const int dst = gw;

    const float a0 = att[lane];
    const float a1 = att[lane + 32];
    const float xr0 = g_xr[dst * 64 + lane];
    const float xr1 = g_xr[dst * 64 + lane + 32];

    const int start = g_off[dst];
    const int cnt   = g_deg[dst];

    float m = -INFINITY, s = 0.f, acc0 = 0.f, acc1 = 0.f;

    // t = 0 is the self-loop; t in [1, cnt] are CSR edges.
    float v0 = g_xl[dst * 64 + lane];
    float v1 = g_xl[dst * 64 + lane + 32];

    for (int t = 0; t <= cnt; ++t) {
        float cv0 = v0, cv1 = v1;
        if (t < cnt) {                      // prefetch next source row
            int sn = g_csr[start + t];
            v0 = g_xl[sn * 64 + lane];
            v1 = g_xl[sn * 64 + lane + 32];
        }
        float h0 = cv0 + xr0; h0 = h0 > 0.f ? h0 : NEG_SLOPE * h0;
        float h1 = cv1 + xr1; h1 = h1 > 0.f ? h1 : NEG_SLOPE * h1;
        float p = a0 * h0 + a1 * h1;
#pragma unroll
        for (int o = 16; o; o >>= 1) p += __shfl_xor_sync(0xffffffffu, p, o);

        float mn = fmaxf(m, p);
        float cs = __expf(m - mn);   // 0 on the first iteration (m = -inf)
        float ce = __expf(p - mn);
        s    = s * cs + ce;
        acc0 = acc0 * cs + ce * cv0;
        acc1 = acc1 * cs + ce * cv1;
        m = mn;
    }

    float inv = 1.f / s;
    out[dst * 64 + lane]      = fmaxf(acc0 * inv + bias[lane], 0.f);
    out[dst * 64 + lane + 32] = fmaxf(acc1 * inv + bias[lane + 32], 0.f);
}

// ---------------- launch ------------------------------------------------------
extern "C" void kernel_launch(void* const* d_in, const int* in_sizes, int n_in,
                              void* d_out, int out_size) {
    const float* x    = (const float*)d_in[0];
    const float* Wl   = (const float*)d_in[1];
    const float* bl   = (const float*)d_in[2];
    const float* Wr   = (const float*)d_in[3];
    const float* br   = (const float*)d_in[4];
    const float* att  = (const float*)d_in[5];
    const float* bias = (const float*)d_in[6];
    const void*  ei   = (const void*)d_in[7];
    float* out = (float*)d_out;

    init_kernel<<<NB_SCAN, 1024>>>(ei);
    gemm_kernel<<<(NNODE + 31) / 32, 256>>>(x, Wl, bl, Wr, br);
    deg_kernel<<<1184, 256>>>(ei);
    scan_kernel<<<NB_SCAN, 1024>>>();
    fixup_kernel<<<NB_SCAN, 1024>>>();
    scatter_kernel<<<1184, 256>>>(ei);
    aggregate_kernel<<<(NNODE * 32 + 255) / 256, 256>>>(att, bias, out);
}

// round 6
// speedup vs baseline: 1.8846x; 1.0596x over previous
#include <cuda_runtime.h>
#include <math.h>
#include <stdint.h>

#define NNODE 50000
#define NEDGE 800000
#define FIN   128
#define FOUT  64
#define NEG_SLOPE 0.2f
#define NB_SCAN 49            // ceil(NNODE/1024)

// ---------------- scratch (device globals: no allocation allowed) -------------
__device__ float g_xl[NNODE * FOUT];
__device__ float g_xr[NNODE * FOUT];
__device__ int   g_deg[NNODE];
__device__ int   g_off[NNODE];
__device__ int   g_cursor[NNODE];
__device__ int   g_csr[NEDGE];
__device__ int   g_bsum[NB_SCAN];
__device__ int   g_is64;

// ---------------- init: zero counters + detect edge_index dtype --------------
__global__ void init_kernel(const void* __restrict__ ei) {
    int i = blockIdx.x * blockDim.x + threadIdx.x;
    for (int k = i; k < NNODE; k += gridDim.x * blockDim.x) {
        g_deg[k] = 0;
        g_cursor[k] = 0;
    }
    if (blockIdx.x == 0 && threadIdx.x < 32) {
        const long long* p = (const long long*)ei;
        int lane = threadIdx.x;
        int ok = 1;
#pragma unroll
        for (int j = 0; j < 8; ++j) {
            long long v = p[lane * 8 + j];
            if (v < 0 || v >= (long long)NNODE) ok = 0;
        }
        unsigned all = __ballot_sync(0xffffffffu, ok);
        if (lane == 0) g_is64 = (all == 0xffffffffu) ? 1 : 0;
    }
}

// ---------------- 3xTF32 tensor-core GEMM (48KB static smem) ------------------
// Per block: 256 thr (8 warps), 32 X-rows, two passes (Wl half, Wr half).
// Warp w: m-tile = (w>>2)*16 rows, n-tile = (w&3)*16 cols (2 n8 frags).
// Smem float4 cells with XOR swizzle: cell(r,c4) -> r*32 + (c4 ^ (r&7)).
// 3xTF32: v = hi + lo (both tf32); acc += hi*hi + hi*lo + lo*hi.

__device__ __forceinline__ void tf32_split(float v, uint32_t& hi, uint32_t& lo) {
    asm("cvt.rna.tf32.f32 %0, %1;" : "=r"(hi) : "f"(v));
    float l = v - __uint_as_float(hi);
    asm("cvt.rna.tf32.f32 %0, %1;" : "=r"(lo) : "f"(l));
}

__device__ __forceinline__ void mma_tf32(float c[4], const uint32_t a[4],
                                         uint32_t b0, uint32_t b1) {
    asm volatile(
        "mma.sync.aligned.m16n8k8.row.col.f32.tf32.tf32.f32 "
        "{%0,%1,%2,%3}, {%4,%5,%6,%7}, {%8,%9}, {%0,%1,%2,%3};"
        : "+f"(c[0]), "+f"(c[1]), "+f"(c[2]), "+f"(c[3])
        : "r"(a[0]), "r"(a[1]), "r"(a[2]), "r"(a[3]), "r"(b0), "r"(b1));
}

__global__ void __launch_bounds__(256) gemm_kernel(
        const float* __restrict__ x,
        const float* __restrict__ Wl,
        const float* __restrict__ bl,
        const float* __restrict__ Wr,
        const float* __restrict__ br) {
    __shared__ float4 sX4[32 * 32];   // 16 KB: 32 rows x 128 k
    __shared__ float4 sW4[64 * 32];   // 32 KB: 64 cols x 128 k (one W half)

    const int tid = threadIdx.x;
    const int rowBase = blockIdx.x * 32;

    const float4* x4 = (const float4*)x;
    for (int i = tid; i < 32 * 32; i += 256) {
        int r = i >> 5, c = i & 31;
        int row = rowBase + r;
        sX4[r * 32 + (c ^ (r & 7))] =
            (row < NNODE) ? x4[row * 32 + c] : make_float4(0.f, 0.f, 0.f, 0.f);
    }

    const int w    = tid >> 5;
    const int lane = tid & 31;
    const int g    = lane >> 2;    // 0..7
    const int tig  = lane & 3;     // 0..3
    const int mw   = (w >> 2) * 16;
    const int nw   = (w & 3) * 16;

#pragma unroll
    for (int p = 0; p < 2; ++p) {
        const float4* w4 = p ? (const float4*)Wr : (const float4*)Wl;
        __syncthreads();   // protect sW reuse (and pass-0 sX visibility)
        for (int i = tid; i < 64 * 32; i += 256) {
            int r = i >> 5, c = i & 31;
            sW4[r * 32 + (c ^ (r & 7))] = w4[r * 32 + c];
        }
        __syncthreads();

        float acc[2][4];
#pragma unroll
        for (int j = 0; j < 2; ++j)
#pragma unroll
            for (int q = 0; q < 4; ++q) acc[j][q] = 0.f;

        const int r0 = mw + g, r1 = mw + 8 + g;

#pragma unroll
        for (int ks = 0; ks < 16; ++ks) {
            const int c4a = 2 * ks;
            const int c4b = 2 * ks + 1;
            float af[4];
            af[0] = ((const float*)&sX4[r0 * 32 + (c4a ^ (r0 & 7))])[tig];
            af[1] = ((const float*)&sX4[r1 * 32 + (c4a ^ (r1 & 7))])[tig];
            af[2] = ((const float*)&sX4[r0 * 32 + (c4b ^ (r0 & 7))])[tig];
            af[3] = ((const float*)&sX4[r1 * 32 + (c4b ^ (r1 & 7))])[tig];
            uint32_t ahi[4], alo[4];
#pragma unroll
            for (int q = 0; q < 4; ++q) tf32_split(af[q], ahi[q], alo[q]);

#pragma unroll
            for (int j = 0; j < 2; ++j) {
                const int br_ = nw + j * 8 + g;
                float b0f = ((const float*)&sW4[br_ * 32 + (c4a ^ (br_ & 7))])[tig];
                float b1f = ((const float*)&sW4[br_ * 32 + (c4b ^ (br_ & 7))])[tig];
                uint32_t b0h, b0l, b1h, b1l;
                tf32_split(b0f, b0h, b0l);
                tf32_split(b1f, b1h, b1l);
                mma_tf32(acc[j], ahi, b0h, b1h);   // hi*hi
                mma_tf32(acc[j], ahi, b0l, b1l);   // hi*lo
                mma_tf32(acc[j], alo, b0h, b1h);   // lo*hi
            }
        }

        float* dstbuf = p ? g_xr : g_xl;
        const float* bb = p ? br : bl;
#pragma unroll
        for (int j = 0; j < 2; ++j) {
            int cc = nw + j * 8 + 2 * tig;
            float bias0 = bb[cc], bias1 = bb[cc + 1];
            int row0 = rowBase + mw + g;
            if (row0 < NNODE) {
                float2 o = make_float2(acc[j][0] + bias0, acc[j][1] + bias1);
                *(float2*)(dstbuf + row0 * 64 + cc) = o;
            }
            int row1 = row0 + 8;
            if (row1 < NNODE) {
                float2 o = make_float2(acc[j][2] + bias0, acc[j][3] + bias1);
                *(float2*)(dstbuf + row1 * 64 + cc) = o;
            }
        }
    }
}

// ---------------- degree histogram -------------------------------------------
__global__ void deg_kernel(const void* __restrict__ ei) {
    const int stride = gridDim.x * blockDim.x;
    const int is64 = g_is64;
    for (int i = blockIdx.x * blockDim.x + threadIdx.x; i < NEDGE; i += stride) {
        int d;
        if (is64) d = (int)((const long long*)ei)[NEDGE + i];
        else      d = ((const int*)ei)[NEDGE + i];
        atomicAdd(&g_deg[d], 1);
    }
}

// ---------------- per-block scan of degrees ----------------------------------
__global__ void scan_kernel() {
    int i = blockIdx.x * 1024 + threadIdx.x;
    int v = (i < NNODE) ? g_deg[i] : 0;
    int xx = v;
    int lane = threadIdx.x & 31, wid = threadIdx.x >> 5;
#pragma unroll
    for (int o = 1; o < 32; o <<= 1) {
        int y = __shfl_up_sync(0xffffffffu, xx, o);
        if (lane >= o) xx += y;
    }
    __shared__ int ws[32];
    if (lane == 31) ws[wid] = xx;
    __syncthreads();
    if (wid == 0) {
        int y = ws[lane];
#pragma unroll
        for (int o = 1; o < 32; o <<= 1) {
            int z = __shfl_up_sync(0xffffffffu, y, o);
            if (lane >= o) y += z;
        }
        ws[lane] = y;
    }
    __syncthreads();
    int incl = xx + (wid ? ws[wid - 1] : 0);
    if (i < NNODE) g_off[i] = incl - v;                  // block-local exclusive
    if (threadIdx.x == 1023) g_bsum[blockIdx.x] = incl;  // block total
}

// ---------------- fixup: inter-block prefix (computed redundantly) + add -----
__global__ void fixup_kernel() {
    __shared__ int pref;
    if (threadIdx.x == 0) {
        int run = 0;
        for (int b = 0; b < blockIdx.x; ++b) run += g_bsum[b];
        pref = run;
    }
    __syncthreads();
    int i = blockIdx.x * 1024 + threadIdx.x;
    if (i < NNODE) g_off[i] += pref;
}

// ---------------- scatter edges into CSR (by dst) ----------------------------
__global__ void scatter_kernel(const void* __restrict__ ei) {
    const int stride = gridDim.x * blockDim.x;
    const int is64 = g_is64;
    for (int i = blockIdx.x * blockDim.x + threadIdx.x; i < NEDGE; i += stride) {
        int s, d;
        if (is64) {
            s = (int)((const long long*)ei)[i];
            d = (int)((const long long*)ei)[NEDGE + i];
        } else {
            s = ((const int*)ei)[i];
            d = ((const int*)ei)[NEDGE + i];
        }
        int pos = atomicAdd(&g_cursor[d], 1);
        g_csr[g_off[d] + pos] = s;
    }
}

// ---------------- aggregation: one warp per dst, online softmax (float2) ------
__global__ void aggregate_kernel(const float* __restrict__ att,
                                 const float* __restrict__ bias,
                                 float* __restrict__ out) {
    int gw   = (blockIdx.x * blockDim.x + threadIdx.x) >> 5;
    int lane = threadIdx.x & 31;
    if (gw >= NNODE) return;
    const int dst = gw;

    const float2* xl2 = (const float2*)g_xl;   // row = 32 float2
    const float2 a    = ((const float2*)att)[lane];
    const float2 xr   = ((const float2*)g_xr)[dst * 32 + lane];

    const int start = g_off[dst];
    const int cnt   = g_deg[dst];

    float m = -INFINITY, s = 0.f;
    float2 acc = make_float2(0.f, 0.f);

    // t = 0 is the self-loop; t in [1, cnt] are CSR edges.
    float2 v = xl2[dst * 32 + lane];

    for (int t = 0; t <= cnt; ++t) {
        float2 cv = v;
        if (t < cnt) {                      // prefetch next source row
            int sn = g_csr[start + t];
            v = xl2[sn * 32 + lane];
        }
        float h0 = cv.x + xr.x; h0 = h0 > 0.f ? h0 : NEG_SLOPE * h0;
        float h1 = cv.y + xr.y; h1 = h1 > 0.f ? h1 : NEG_SLOPE * h1;
        float p = a.x * h0 + a.y * h1;
#pragma unroll
        for (int o = 16; o; o >>= 1) p += __shfl_xor_sync(0xffffffffu, p, o);

        float mn = fmaxf(m, p);
        float cs = __expf(m - mn);   // 0 on the first iteration (m = -inf)
        float ce = __expf(p - mn);
        s     = s * cs + ce;
        acc.x = acc.x * cs + ce * cv.x;
        acc.y = acc.y * cs + ce * cv.y;
        m = mn;
    }

    float inv = 1.f / s;
    float2 bv = ((const float2*)bias)[lane];
    float2 o = make_float2(fmaxf(acc.x * inv + bv.x, 0.f),
                           fmaxf(acc.y * inv + bv.y, 0.f));
    ((float2*)out)[dst * 32 + lane] = o;
}

// ---------------- launch: fork GEMM || CSR build, join before aggregate -------
extern "C" void kernel_launch(void* const* d_in, const int* in_sizes, int n_in,
                              void* d_out, int out_size) {
    const float* x    = (const float*)d_in[0];
    const float* Wl   = (const float*)d_in[1];
    const float* bl   = (const float*)d_in[2];
    const float* Wr   = (const float*)d_in[3];
    const float* br   = (const float*)d_in[4];
    const float* att  = (const float*)d_in[5];
    const float* bias = (const float*)d_in[6];
    const void*  ei   = (const void*)d_in[7];
    float* out = (float*)d_out;

    cudaStream_t s2;
    cudaEvent_t evFork, evJoin;
    cudaStreamCreateWithFlags(&s2, cudaStreamNonBlocking);
    cudaEventCreateWithFlags(&evFork, cudaEventDisableTiming);
    cudaEventCreateWithFlags(&evJoin, cudaEventDisableTiming);

    // Root work on the (captured) default stream.
    init_kernel<<<NB_SCAN, 1024>>>(ei);
    cudaEventRecord(evFork, 0);

    // Side stream: CSR build (depends only on init + edge_index).
    cudaStreamWaitEvent(s2, evFork, 0);
    deg_kernel<<<1184, 256, 0, s2>>>(ei);
    scan_kernel<<<NB_SCAN, 1024, 0, s2>>>();
    fixup_kernel<<<NB_SCAN, 1024, 0, s2>>>();
    scatter_kernel<<<1184, 256, 0, s2>>>(ei);
    cudaEventRecord(evJoin, s2);

    // Main stream: GEMM runs concurrently with the CSR build.
    gemm_kernel<<<(NNODE + 31) / 32, 256>>>(x, Wl, bl, Wr, br);

    // Join, then aggregate (needs both xl/xr and the CSR).
    cudaStreamWaitEvent(0, evJoin, 0);
    aggregate_kernel<<<(NNODE * 32 + 255) / 256, 256>>>(att, bias, out);

    cudaEventDestroy(evFork);
    cudaEventDestroy(evJoin);
    cudaStreamDestroy(s2);
}